// round 3
// baseline (speedup 1.0000x reference)
#include <cuda_runtime.h>
#include <float.h>

// Problem constants
#define DIMS      256      // embedding dim
#define KCODES    1024     // num embeddings
#define HWSZ      1024     // H*W = 32*32
#define BATCH     32
#define NROWS     32768    // BATCH * HWSZ
#define NUMEL     8388608  // BATCH * DIMS * HWSZ

// Tiling
#define TM        64       // rows per CTA
#define TK        128      // codes per k-tile
#define TD        16       // d-chunk per pipeline step
#define NTHREADS  256
#define WS_STRIDE 132      // TK + 4 pad (2-way instead of 16-way STS conflicts)
#define NTILES    128      // (KCODES/TK) * (DIMS/TD) = 8 * 16

__device__ float g_wsq[KCODES];
__device__ float g_loss;

// ---------------------------------------------------------------------------
// Kernel 1: ||w_k||^2 per code (one warp per code), and zero the loss accum.
// ---------------------------------------------------------------------------
__global__ void vq_wsq_kernel(const float* __restrict__ w) {
    if (blockIdx.x == 0 && threadIdx.x == 0) g_loss = 0.0f;
    int warp = threadIdx.x >> 5;
    int lane = threadIdx.x & 31;
    int k = blockIdx.x * 8 + warp;       // 256 threads = 8 warps per block
    if (k >= KCODES) return;
    const float* row = w + (size_t)k * DIMS;
    float s = 0.0f;
    #pragma unroll
    for (int j = 0; j < DIMS / 32; j++) {
        float v = row[lane + j * 32];
        s += v * v;
    }
    #pragma unroll
    for (int off = 16; off > 0; off >>= 1)
        s += __shfl_xor_sync(0xFFFFFFFFu, s, off);
    if (lane == 0) g_wsq[k] = s;
}

// ---------------------------------------------------------------------------
// Kernel 2: fused distance-GEMM + argmin + codebook gather + loss + output.
// Each CTA owns 64 rows (contiguous hw positions of one batch image) and
// scans all 1024 codes.  fp32 FFMA throughout (argmin must match fp32 ref).
// ---------------------------------------------------------------------------
__global__ void __launch_bounds__(NTHREADS)
vq_main_kernel(const float* __restrict__ x,   // [B, D, HW] (NCHW)
               const float* __restrict__ w,   // [K, D]
               float* __restrict__ out)       // [B, D, HW]
{
    __shared__ __align__(16) float As[2][TD][TM];          // 8 KB
    __shared__ __align__(16) float Ws[2][TD][WS_STRIDE];   // 16.5 KB
    __shared__ float wsq_s[KCODES];                        // 4 KB
    __shared__ int   sidx[TM];

    const int tid = threadIdx.x;
    const int tx  = tid & 15;    // code-dim thread coord (8 codes each)
    const int ty  = tid >> 4;    // row-dim thread coord (4 rows each)

    const int tile = blockIdx.x;         // 0..511
    const int b    = tile >> 4;
    const int hw0  = (tile & 15) * TM;
    const float* xb = x + (size_t)b * DIMS * HWSZ + hw0;

    // wsq -> smem (needed for every epilogue)
    #pragma unroll
    for (int i = tid; i < KCODES; i += NTHREADS) wsq_s[i] = g_wsq[i];

    // per-thread running argmin for its 4 rows
    float bestv[4] = {FLT_MAX, FLT_MAX, FLT_MAX, FLT_MAX};
    int   besti[4] = {0, 0, 0, 0};

    // ---- software pipeline: global -> regs -> smem, double buffered ----
    const int a_dd0 = tid >> 6;      // loadA: dd = a_dd0 + j*4, m = a_m
    const int a_m   = tid & 63;
    const int w_dd  = tid & 15;      // loadW: kk = w_kk0 + j*16
    const int w_kk0 = tid >> 4;

    float ra[4], rw[8];

    // preload tile 0 (kt=0, ds=0)
    #pragma unroll
    for (int j = 0; j < 4; j++)
        ra[j] = xb[(a_dd0 + j * 4) * HWSZ + a_m];
    {
        const float* wb = w;  // kt=0, ds=0
        #pragma unroll
        for (int j = 0; j < 8; j++)
            rw[j] = wb[(w_kk0 + j * 16) * DIMS + w_dd];
    }
    #pragma unroll
    for (int j = 0; j < 4; j++) As[0][a_dd0 + j * 4][a_m] = ra[j];
    #pragma unroll
    for (int j = 0; j < 8; j++) Ws[0][w_dd][w_kk0 + j * 16] = rw[j];
    __syncthreads();

    int buf = 0;
    #pragma unroll 1
    for (int kt = 0; kt < KCODES / TK; kt++) {
        float acc[4][8];
        #pragma unroll
        for (int mi = 0; mi < 4; mi++)
            #pragma unroll
            for (int ki = 0; ki < 8; ki++) acc[mi][ki] = 0.0f;

        #pragma unroll 1
        for (int ds = 0; ds < DIMS / TD; ds++) {
            const int t  = kt * 16 + ds;
            const int nt = t + 1;
            if (nt < NTILES) {
                const int nkt = nt >> 4, nds = nt & 15;
                #pragma unroll
                for (int j = 0; j < 4; j++)
                    ra[j] = xb[(nds * TD + a_dd0 + j * 4) * HWSZ + a_m];
                const float* wb = w + (size_t)(nkt * TK) * DIMS + nds * TD;
                #pragma unroll
                for (int j = 0; j < 8; j++)
                    rw[j] = wb[(w_kk0 + j * 16) * DIMS + w_dd];
            }

            // compute on current buffer: 16 d-steps x (4x8) FMAs
            #pragma unroll
            for (int dd = 0; dd < TD; dd++) {
                float4 av = *(const float4*)&As[buf][dd][ty * 4];
                float4 b0 = *(const float4*)&Ws[buf][dd][tx * 8];
                float4 b1 = *(const float4*)&Ws[buf][dd][tx * 8 + 4];
                float a_[4] = {av.x, av.y, av.z, av.w};
                float b_[8] = {b0.x, b0.y, b0.z, b0.w, b1.x, b1.y, b1.z, b1.w};
                #pragma unroll
                for (int mi = 0; mi < 4; mi++)
                    #pragma unroll
                    for (int ki = 0; ki < 8; ki++)
                        acc[mi][ki] = fmaf(a_[mi], b_[ki], acc[mi][ki]);
            }

            if (nt < NTILES) {
                const int nb = buf ^ 1;
                #pragma unroll
                for (int j = 0; j < 4; j++) As[nb][a_dd0 + j * 4][a_m] = ra[j];
                #pragma unroll
                for (int j = 0; j < 8; j++) Ws[nb][w_dd][w_kk0 + j * 16] = rw[j];
            }
            __syncthreads();
            buf ^= 1;
        }

        // epilogue for this k-tile: dist = ||w||^2 - 2*dot ; running argmin
        const int kb = kt * TK + tx * 8;
        #pragma unroll
        for (int mi = 0; mi < 4; mi++) {
            #pragma unroll
            for (int ki = 0; ki < 8; ki++) {
                float dist = wsq_s[kb + ki] - 2.0f * acc[mi][ki];
                int   idx  = kb + ki;
                // ascending scan: strict < keeps earliest; == tie -> lower idx
                if (dist < bestv[mi] ||
                    (dist == bestv[mi] && idx < besti[mi])) {
                    bestv[mi] = dist;
                    besti[mi] = idx;
                }
            }
        }
    }

    // ---- cross-thread argmin reduction (16 tx threads per row) ----
    __syncthreads();
    float* redv = (float*)Ws;            // reuse Ws as scratch (done with it)
    int*   redi = (int*)((float*)Ws + TM * 16);
    #pragma unroll
    for (int mi = 0; mi < 4; mi++) {
        int m = ty * 4 + mi;
        redv[m * 16 + tx] = bestv[mi];
        redi[m * 16 + tx] = besti[mi];
    }
    __syncthreads();
    if (tid < TM) {
        float bv = FLT_MAX; int bi = 0x7FFFFFFF;
        #pragma unroll
        for (int j = 0; j < 16; j++) {
            float v = redv[tid * 16 + j];
            int   i = redi[tid * 16 + j];
            if (v < bv || (v == bv && i < bi)) { bv = v; bi = i; }
        }
        sidx[tid] = bi;
    }
    __syncthreads();

    // ---- gather codebook rows, write NCHW output, accumulate loss ----
    float* outb = out + (size_t)b * DIMS * HWSZ + hw0;
    float lsum = 0.0f;
    #pragma unroll 1
    for (int i = tid; i < TM * (DIMS / 4); i += NTHREADS) {
        int m  = i & 63;          // lanes -> consecutive m: coalesced x/out
        int dc = i >> 6;
        float4 q = *(const float4*)&w[(size_t)sidx[m] * DIMS + dc * 4];
        float qv[4] = {q.x, q.y, q.z, q.w};
        #pragma unroll
        for (int j = 0; j < 4; j++) {
            int d = dc * 4 + j;
            float xv = xb[d * HWSZ + m];
            float df = qv[j] - xv;
            lsum = fmaf(df, df, lsum);
            outb[d * HWSZ + m] = qv[j];
        }
    }

    // block-reduce loss, one atomic per CTA
    #pragma unroll
    for (int off = 16; off > 0; off >>= 1)
        lsum += __shfl_xor_sync(0xFFFFFFFFu, lsum, off);
    __syncthreads();
    float* lred = (float*)Ws;
    if ((tid & 31) == 0) lred[tid >> 5] = lsum;
    __syncthreads();
    if (tid == 0) {
        float s = 0.0f;
        #pragma unroll
        for (int j = 0; j < NTHREADS / 32; j++) s += lred[j];
        atomicAdd(&g_loss, s);
    }
}

// ---------------------------------------------------------------------------
// Kernel 3: finalize loss scalar -> tail of output buffer.
// loss = codebook_loss + 0.25*commit_loss = 1.25 * mean((q-x)^2)
// ---------------------------------------------------------------------------
__global__ void vq_finalize_kernel(float* __restrict__ out, int out_size) {
    if (out_size > NUMEL)
        out[NUMEL] = g_loss * (1.25f / (float)NUMEL);
}

// ---------------------------------------------------------------------------
extern "C" void kernel_launch(void* const* d_in, const int* in_sizes, int n_in,
                              void* d_out, int out_size) {
    const float* x = (const float*)d_in[0];   // [32, 256, 32, 32] fp32
    const float* w = (const float*)d_in[1];   // [1024, 256] fp32
    float* out = (float*)d_out;

    vq_wsq_kernel<<<KCODES / 8, 256>>>(w);
    vq_main_kernel<<<NROWS / TM, NTHREADS>>>(x, w, out);
    vq_finalize_kernel<<<1, 1>>>(out, out_size);
}